// round 2
// baseline (speedup 1.0000x reference)
#include <cuda_runtime.h>
#include <cuda_bf16.h>
#include <cstdint>

// ============================================================================
// Conv2D per-sample dynamic filter via warp-level mma.sync (tf32 HMMA).
//   out[b,y,x,co] = sum_{dy,dx,ci} X[b,y+dy,x+dx,ci] * K[b,dy,dx,ci,co]
//
// Family-level sm_103 target: NO tcgen05 / TMEM / cta_group (rejected by
// ptxas at .target sm_103). Use mma.sync.m16n8k8.tf32 instead.
//
// CTA = (y, b): output row tile M=128 (pixels x, rows 126..127 garbage),
// N=128 (Cout). K-loop: 12 stages = 3 dy x 4 ci-chunks(32); within a stage,
// dx in {0,1,2} shifts the A-fragment SMEM row address (px = m + dx, clamped),
// so A is staged once per stage while accumulating all 3 dx taps.
// ============================================================================

#define THREADS 256

// tf32(RNA)-rounded X copy                          (128 MB device scratch)
__device__ float g_Xr[16 * 128 * 128 * 128];
// filter in mma-B fragment order, tf32-rounded:
//   [b][dy][ci_chunk(4)][dx(3)][j(4)][p(8)][lane(32)][4 floats]
__device__ float g_Kf[16 * 9 * 128 * 128];

static __device__ __forceinline__ uint32_t smem_u32(const void* p) {
    uint32_t a;
    asm("{ .reg .u64 t; cvta.to.shared.u64 t, %1; cvt.u32.u64 %0, t; }"
        : "=r"(a) : "l"(p));
    return a;
}

static __device__ __forceinline__ uint32_t f32_tf32(float f) {
    uint32_t r;
    asm("cvt.rna.tf32.f32 %0, %1;" : "=r"(r) : "f"(f));
    return r;
}

static __device__ __forceinline__ void cp16(uint32_t dst, const void* src) {
    asm volatile("cp.async.cg.shared.global [%0], [%1], 16;"
                 :: "r"(dst), "l"(src) : "memory");
}

#define CP_COMMIT() asm volatile("cp.async.commit_group;" ::: "memory")
#define CP_WAIT1()  asm volatile("cp.async.wait_group 1;" ::: "memory")

// D += A * B   (m16n8k8, tf32, row.col)
#define MMA(d, a, b0, b1)                                                     \
    asm volatile(                                                             \
        "mma.sync.aligned.m16n8k8.row.col.f32.tf32.tf32.f32 "                 \
        "{%0,%1,%2,%3}, {%4,%5,%6,%7}, {%8,%9}, {%0,%1,%2,%3};"               \
        : "+f"((d)[0]), "+f"((d)[1]), "+f"((d)[2]), "+f"((d)[3])              \
        : "r"((a)[0]), "r"((a)[1]), "r"((a)[2]), "r"((a)[3]),                 \
          "r"(b0), "r"(b1))

// ---------------- pre-pass 1: RNA tf32-round X ------------------------------

__global__ void __launch_bounds__(256) round_x(const float4* __restrict__ X, int n4) {
    int stride = gridDim.x * blockDim.x;
    for (int i = blockIdx.x * blockDim.x + threadIdx.x; i < n4; i += stride) {
        float4 v = X[i];
        uint4 t;
        t.x = f32_tf32(v.x); t.y = f32_tf32(v.y);
        t.z = f32_tf32(v.z); t.w = f32_tf32(v.w);
        reinterpret_cast<uint4*>(g_Xr)[i] = t;
    }
}

// ---------------- pre-pass 2: filter -> fragment order ----------------------
// One thread per dest float4 = one (b,dy,c,dx,j,p,lane) cell.
// Fragment (m16n8k8 tf32, col-major B): b0 = B[k=t][n=g], b1 = B[k=t+4][n=g].
// float4 packs (b0,b1) of n8-tile 2p and (b0,b1) of n8-tile 2p+1.

__global__ void __launch_bounds__(256) kt_frag(const float* __restrict__ K) {
    int id = blockIdx.x * 256 + threadIdx.x;          // 0 .. 589823
    int lane = id & 31;
    int r = id >> 5;
    int p  = r & 7;  r >>= 3;
    int j  = r & 3;  r >>= 2;
    int dx = r % 3;  r /= 3;
    int c  = r & 3;  r >>= 2;
    int dy = r % 3;
    int b  = r / 3;
    int g = lane >> 2, t = lane & 3;
    int ci = c * 32 + j * 8 + t;
    int co = p * 16 + g;
    const float* src = K + ((size_t)(b * 9 + dy * 3 + dx) * 128) * 128;
    uint4 v;
    v.x = f32_tf32(src[(size_t)ci * 128 + co]);
    v.y = f32_tf32(src[(size_t)(ci + 4) * 128 + co]);
    v.z = f32_tf32(src[(size_t)ci * 128 + co + 8]);
    v.w = f32_tf32(src[(size_t)(ci + 4) * 128 + co + 8]);
    reinterpret_cast<uint4*>(g_Kf)[id] = v;
}

// ---------------- main kernel ----------------------------------------------

static constexpr int A_STRIDE_F = 36;                  // 32 floats + 4 pad
static constexpr int A_BYTES    = 128 * A_STRIDE_F * 4;  // 18432
static constexpr int B_BYTES    = 3 * 4 * 8 * 32 * 16;   // 49152
static constexpr int BUF_BYTES  = A_BYTES + B_BYTES;     // 67584
static constexpr int SMEM_TOTAL = 2 * BUF_BYTES;         // 135168

__global__ void __launch_bounds__(THREADS) conv_main(float* __restrict__ out) {
    extern __shared__ char smem[];
    const uint32_t smem_base = smem_u32(smem);
    const int tid  = threadIdx.x;
    const int lane = tid & 31;
    const int wid  = tid >> 5;
    const int warp_m = wid & 3;           // 4 warps along M (32 rows each)
    const int warp_n = wid >> 2;          // 2 warps along N (64 cols each)
    const int g = lane >> 2, t = lane & 3;
    const int y = blockIdx.x;             // output row 0..125
    const int b = blockIdx.y;             // batch

    // ---- stage loader: stage s = (dy = s>>2, ci chunk c = s&3) ----
    auto stage_load = [&](int s, int buf) {
        const int dy = s >> 2;
        const int c  = s & 3;
        const uint32_t abase = smem_base + buf * BUF_BYTES;
        const float* Arow = g_Xr + (((size_t)b * 128 + (y + dy)) * 128) * 128 + c * 32;
#pragma unroll
        for (int i = 0; i < 4; i++) {
            int idx = tid + i * THREADS;          // 0..1023
            int px = idx >> 3, ch = idx & 7;      // 8 x 16B per 32-float slice
            cp16(abase + px * (A_STRIDE_F * 4) + ch * 16,
                 Arow + (size_t)px * 128 + ch * 4);
        }
        const float* Bsrc = g_Kf + ((size_t)((b * 3 + dy) * 4 + c)) * 12288;
        const uint32_t bbase = abase + A_BYTES;
#pragma unroll
        for (int i = 0; i < 12; i++) {
            int idx = tid + i * THREADS;          // 0..3071
            cp16(bbase + idx * 16, Bsrc + (size_t)idx * 4);
        }
    };

    float acc[2][8][4];
#pragma unroll
    for (int mt = 0; mt < 2; mt++)
#pragma unroll
        for (int nt = 0; nt < 8; nt++)
#pragma unroll
            for (int e = 0; e < 4; e++) acc[mt][nt][e] = 0.0f;

    stage_load(0, 0); CP_COMMIT();
    stage_load(1, 1); CP_COMMIT();

    const int rbase = warp_m * 32 + g;

    for (int s = 0; s < 12; s++) {
        CP_WAIT1();
        __syncthreads();

        const int buf = s & 1;
        const uint32_t* Au = reinterpret_cast<const uint32_t*>(smem + buf * BUF_BYTES);
        const float4*   Bs = reinterpret_cast<const float4*>(smem + buf * BUF_BYTES + A_BYTES);

#pragma unroll
        for (int dx = 0; dx < 3; dx++) {
            // A-fragment SMEM rows: px = m + dx, clamped to 127 (rows >=126 are
            // garbage outputs; clamp keeps addresses in the tile).
            int p0 = min(rbase + dx,      127) * A_STRIDE_F;
            int p1 = min(rbase + dx + 8,  127) * A_STRIDE_F;
            int p2 = min(rbase + dx + 16, 127) * A_STRIDE_F;
            int p3 = min(rbase + dx + 24, 127) * A_STRIDE_F;
#pragma unroll
            for (int j = 0; j < 4; j++) {
                const int col = j * 8 + t;
                uint32_t a0[4], a1[4];
                a0[0] = Au[p0 + col];     a0[1] = Au[p1 + col];
                a0[2] = Au[p0 + col + 4]; a0[3] = Au[p1 + col + 4];
                a1[0] = Au[p2 + col];     a1[1] = Au[p3 + col];
                a1[2] = Au[p2 + col + 4]; a1[3] = Au[p3 + col + 4];

                float4 bv[4];
#pragma unroll
                for (int pl = 0; pl < 4; pl++)
                    bv[pl] = Bs[(size_t)(((dx * 4 + j) * 8 + warp_n * 4 + pl) * 32 + lane)];

#pragma unroll
                for (int pl = 0; pl < 4; pl++) {
                    uint32_t b0a = __float_as_uint(bv[pl].x), b1a = __float_as_uint(bv[pl].y);
                    uint32_t b0b = __float_as_uint(bv[pl].z), b1b = __float_as_uint(bv[pl].w);
                    MMA(acc[0][2 * pl],     a0, b0a, b1a);
                    MMA(acc[0][2 * pl + 1], a0, b0b, b1b);
                    MMA(acc[1][2 * pl],     a1, b0a, b1a);
                    MMA(acc[1][2 * pl + 1], a1, b0b, b1b);
                }
            }
        }

        __syncthreads();
        if (s + 2 < 12) stage_load(s + 2, buf);
        CP_COMMIT();   // always commit (empty group keeps wait_group math simple)
    }

    // ---- epilogue: direct STG (accumulator rows ARE output x) ----
    float* outp = out + (((size_t)b * 126 + y) * 126) * 128;
#pragma unroll
    for (int mt = 0; mt < 2; mt++) {
        const int x0 = warp_m * 32 + mt * 16 + g;        // always < 126
        const int x1 = x0 + 8;                           // may be 126/127
#pragma unroll
        for (int nt = 0; nt < 8; nt++) {
            const int co = warp_n * 64 + nt * 8 + 2 * t;
            float2 v0 = make_float2(acc[mt][nt][0], acc[mt][nt][1]);
            *reinterpret_cast<float2*>(outp + (size_t)x0 * 128 + co) = v0;
            if (x1 < 126) {
                float2 v1 = make_float2(acc[mt][nt][2], acc[mt][nt][3]);
                *reinterpret_cast<float2*>(outp + (size_t)x1 * 128 + co) = v1;
            }
        }
    }
}

// ---------------- launch ----------------------------------------------------

extern "C" void kernel_launch(void* const* d_in, const int* in_sizes, int n_in,
                              void* d_out, int out_size) {
    const float* X = (const float*)d_in[0];     // [16,128,128,128]
    const float* K = (const float*)d_in[1];     // [16,3,3,128,128]
    float* out = (float*)d_out;                 // [16,126,126,128]
    (void)in_sizes; (void)n_in; (void)out_size;

    cudaFuncSetAttribute(conv_main, cudaFuncAttributeMaxDynamicSharedMemorySize, SMEM_TOTAL);

    round_x<<<4096, 256>>>(reinterpret_cast<const float4*>(X), 16 * 128 * 128 * 32);
    kt_frag<<<2304, 256>>>(K);
    conv_main<<<dim3(126, 16), THREADS, SMEM_TOTAL>>>(out);
}

// round 3
// speedup vs baseline: 1.1073x; 1.1073x over previous
#include <cuda_runtime.h>
#include <cuda_bf16.h>
#include <cstdint>

// ============================================================================
// Conv2D per-sample dynamic filter via warp-level mma.sync (tf32 HMMA).
//   out[b,y,x,co] = sum_{dy,dx,ci} X[b,y+dy,x+dx,ci] * K[b,dy,dx,ci,co]
//
// R2: removed round_x pre-pass (A rounded in-kernel: LDG -> cvt.rna.tf32 ->
// STS with register prefetch); K=16 stages (24 of them); A double-buffered,
// B triple-buffered cp.async; 94KB SMEM -> 2 CTAs/SM; one barrier/stage.
//
// CTA = (y, b): M=128 px x N=128 Cout; dx taps via shifted A-fragment rows.
// ============================================================================

#define THREADS 256

// filter in mma-B fragment order, tf32-rounded:
//   [b][dy][c8(8)][dx(3)][j(2)][p(8)][lane(32)][4 floats]
__device__ float g_Kf[16 * 9 * 128 * 128];

static __device__ __forceinline__ uint32_t smem_u32(const void* p) {
    uint32_t a;
    asm("{ .reg .u64 t; cvta.to.shared.u64 t, %1; cvt.u32.u64 %0, t; }"
        : "=r"(a) : "l"(p));
    return a;
}

static __device__ __forceinline__ uint32_t f32_tf32(float f) {
    uint32_t r;
    asm("cvt.rna.tf32.f32 %0, %1;" : "=r"(r) : "f"(f));
    return r;
}

static __device__ __forceinline__ void cp16(uint32_t dst, const void* src) {
    asm volatile("cp.async.cg.shared.global [%0], [%1], 16;"
                 :: "r"(dst), "l"(src) : "memory");
}

#define CP_COMMIT() asm volatile("cp.async.commit_group;" ::: "memory")
#define CP_WAIT1()  asm volatile("cp.async.wait_group 1;" ::: "memory")

// D += A * B   (m16n8k8, tf32, row.col)
#define MMA(d, a, b0, b1)                                                     \
    asm volatile(                                                             \
        "mma.sync.aligned.m16n8k8.row.col.f32.tf32.tf32.f32 "                 \
        "{%0,%1,%2,%3}, {%4,%5,%6,%7}, {%8,%9}, {%0,%1,%2,%3};"               \
        : "+f"((d)[0]), "+f"((d)[1]), "+f"((d)[2]), "+f"((d)[3])              \
        : "r"((a)[0]), "r"((a)[1]), "r"((a)[2]), "r"((a)[3]),                 \
          "r"(b0), "r"(b1))

// ---------------- pre-pass: filter -> fragment order ------------------------
// One thread per dest float4 = one (b,dy,c8,dx,j,p,lane) cell.
// ci = c8*16 + j*8 + t; co = p*16 + g (and +8 for second n8 tile).

__global__ void __launch_bounds__(256) kt_frag(const float* __restrict__ K) {
    int id = blockIdx.x * 256 + threadIdx.x;          // 0 .. 589823
    int lane = id & 31;
    int r = id >> 5;
    int p  = r & 7;  r >>= 3;
    int j  = r & 1;  r >>= 1;
    int dx = r % 3;  r /= 3;
    int c8 = r & 7;  r >>= 3;
    int dy = r % 3;
    int b  = r / 3;
    int g = lane >> 2, t = lane & 3;
    int ci = c8 * 16 + j * 8 + t;
    int co = p * 16 + g;
    const float* src = K + ((size_t)(b * 9 + dy * 3 + dx) * 128) * 128;
    uint4 v;
    v.x = f32_tf32(src[(size_t)ci * 128 + co]);
    v.y = f32_tf32(src[(size_t)(ci + 4) * 128 + co]);
    v.z = f32_tf32(src[(size_t)ci * 128 + co + 8]);
    v.w = f32_tf32(src[(size_t)(ci + 4) * 128 + co + 8]);
    reinterpret_cast<uint4*>(g_Kf)[id] = v;
}

// ---------------- main kernel ----------------------------------------------

static constexpr int A_STRIDE_F = 20;                    // 16 floats + 4 pad
static constexpr int A_BYTES    = 128 * A_STRIDE_F * 4;  // 10240
static constexpr int B_BYTES    = 3 * 2 * 8 * 32 * 16;   // 24576
static constexpr int SMEM_B0    = 2 * A_BYTES;           // 20480
static constexpr int SMEM_TOTAL = SMEM_B0 + 3 * B_BYTES; // 94208

__global__ void __launch_bounds__(THREADS, 2) conv_main(
    const float* __restrict__ X, float* __restrict__ out) {
    extern __shared__ char smem[];
    const uint32_t smem_base = smem_u32(smem);
    const int tid  = threadIdx.x;
    const int lane = tid & 31;
    const int wid  = tid >> 5;
    const int warp_m = wid & 3;           // 4 warps along M (32 rows each)
    const int warp_n = wid >> 2;          // 2 warps along N (64 cols each)
    const int g = lane >> 2, t = lane & 3;
    const int y = blockIdx.x;             // output row 0..125
    const int b = blockIdx.y;             // batch

    // stage s = (dy = s/8, c8 = s%8); A chunk = X[b, y+dy, 0:128, c8*16 +:16]
    const float* Xbase = X + (((size_t)b * 128 + y) * 128) * 128;

    // per-thread A-chunk addresses: float4 idx = tid + i*256 (i<2)
    const int apx0 = tid >> 2,           ach0 = tid & 3;
    const int apx1 = (tid + 256) >> 2,   ach1 = (tid + 256) & 3;

    auto a_ldg = [&](int s, float4& v0, float4& v1) {
        const int dy = s >> 3, c8 = s & 7;
        const float* Arow = Xbase + (size_t)dy * 128 * 128 + c8 * 16;
        v0 = *reinterpret_cast<const float4*>(Arow + (size_t)apx0 * 128 + ach0 * 4);
        v1 = *reinterpret_cast<const float4*>(Arow + (size_t)apx1 * 128 + ach1 * 4);
    };
    auto a_sts = [&](int buf, const float4& v0, const float4& v1) {
        uint4 t0, t1;
        t0.x = f32_tf32(v0.x); t0.y = f32_tf32(v0.y);
        t0.z = f32_tf32(v0.z); t0.w = f32_tf32(v0.w);
        t1.x = f32_tf32(v1.x); t1.y = f32_tf32(v1.y);
        t1.z = f32_tf32(v1.z); t1.w = f32_tf32(v1.w);
        char* ab = smem + buf * A_BYTES;
        *reinterpret_cast<uint4*>(ab + apx0 * (A_STRIDE_F * 4) + ach0 * 16) = t0;
        *reinterpret_cast<uint4*>(ab + apx1 * (A_STRIDE_F * 4) + ach1 * 16) = t1;
    };
    auto b_cp = [&](int s) {
        const int dy = s >> 3, c8 = s & 7;
        const float* Bsrc = g_Kf + ((size_t)((b * 3 + dy) * 8 + c8)) * 6144;
        const uint32_t bb = smem_base + SMEM_B0 + (s % 3) * B_BYTES;
#pragma unroll
        for (int i = 0; i < 6; i++) {
            int idx = tid + i * THREADS;          // 0..1535 float4s
            cp16(bb + idx * 16, Bsrc + (size_t)idx * 4);
        }
    };

    float acc[2][8][4];
#pragma unroll
    for (int mt = 0; mt < 2; mt++)
#pragma unroll
        for (int nt = 0; nt < 8; nt++)
#pragma unroll
            for (int e = 0; e < 4; e++) acc[mt][nt][e] = 0.0f;

    // ---- prologue ----
    float4 ar0, ar1;
    a_ldg(0, ar0, ar1);
    a_sts(0, ar0, ar1);          // A0 -> buf0
    a_ldg(1, ar0, ar1);          // A1 held in regs
    b_cp(0); CP_COMMIT();
    b_cp(1); CP_COMMIT();

    const int rbase = warp_m * 32 + g;

    for (int s = 0; s < 24; s++) {
        CP_WAIT1();
        __syncthreads();

        // stage A_{s+1} (held in regs) into its buffer; prefetch A_{s+2}
        if (s < 23) a_sts((s + 1) & 1, ar0, ar1);
        if (s < 22) a_ldg(s + 2, ar0, ar1);
        if (s < 22) b_cp(s + 2);
        CP_COMMIT();

        const uint32_t* Au = reinterpret_cast<const uint32_t*>(smem + (s & 1) * A_BYTES);
        const float4*   Bs = reinterpret_cast<const float4*>(smem + SMEM_B0 + (s % 3) * B_BYTES);

#pragma unroll
        for (int dx = 0; dx < 3; dx++) {
            int p0 = min(rbase + dx,      127) * A_STRIDE_F;
            int p1 = min(rbase + dx + 8,  127) * A_STRIDE_F;
            int p2 = min(rbase + dx + 16, 127) * A_STRIDE_F;
            int p3 = min(rbase + dx + 24, 127) * A_STRIDE_F;
#pragma unroll
            for (int j = 0; j < 2; j++) {
                const int col = j * 8 + t;
                uint32_t a0[4], a1[4];
                a0[0] = Au[p0 + col];     a0[1] = Au[p1 + col];
                a0[2] = Au[p0 + col + 4]; a0[3] = Au[p1 + col + 4];
                a1[0] = Au[p2 + col];     a1[1] = Au[p3 + col];
                a1[2] = Au[p2 + col + 4]; a1[3] = Au[p3 + col + 4];

#pragma unroll
                for (int pl = 0; pl < 4; pl++) {
                    float4 bv = Bs[(size_t)(((dx * 2 + j) * 8 + warp_n * 4 + pl) * 32 + lane)];
                    uint32_t b0a = __float_as_uint(bv.x), b1a = __float_as_uint(bv.y);
                    uint32_t b0b = __float_as_uint(bv.z), b1b = __float_as_uint(bv.w);
                    MMA(acc[0][2 * pl],     a0, b0a, b1a);
                    MMA(acc[0][2 * pl + 1], a0, b0b, b1b);
                    MMA(acc[1][2 * pl],     a1, b0a, b1a);
                    MMA(acc[1][2 * pl + 1], a1, b0b, b1b);
                }
            }
        }
        __syncthreads();
    }

    // ---- epilogue: direct STG (accumulator rows ARE output x) ----
    float* outp = out + (((size_t)b * 126 + y) * 126) * 128;
#pragma unroll
    for (int mt = 0; mt < 2; mt++) {
        const int x0 = warp_m * 32 + mt * 16 + g;        // always < 126
        const int x1 = x0 + 8;                           // may be 126/127
#pragma unroll
        for (int nt = 0; nt < 8; nt++) {
            const int co = warp_n * 64 + nt * 8 + 2 * t;
            float2 v0 = make_float2(acc[mt][nt][0], acc[mt][nt][1]);
            *reinterpret_cast<float2*>(outp + (size_t)x0 * 128 + co) = v0;
            if (x1 < 126) {
                float2 v1 = make_float2(acc[mt][nt][2], acc[mt][nt][3]);
                *reinterpret_cast<float2*>(outp + (size_t)x1 * 128 + co) = v1;
            }
        }
    }
}

// ---------------- launch ----------------------------------------------------

extern "C" void kernel_launch(void* const* d_in, const int* in_sizes, int n_in,
                              void* d_out, int out_size) {
    const float* X = (const float*)d_in[0];     // [16,128,128,128]
    const float* K = (const float*)d_in[1];     // [16,3,3,128,128]
    float* out = (float*)d_out;                 // [16,126,126,128]
    (void)in_sizes; (void)n_in; (void)out_size;

    cudaFuncSetAttribute(conv_main, cudaFuncAttributeMaxDynamicSharedMemorySize, SMEM_TOTAL);

    kt_frag<<<2304, 256>>>(K);
    conv_main<<<dim3(126, 16), THREADS, SMEM_TOTAL>>>(X, out);
}

// round 4
// speedup vs baseline: 1.7416x; 1.5727x over previous
#include <cuda_runtime.h>
#include <cuda_fp16.h>
#include <cstdint>

// ============================================================================
// Conv2D per-sample dynamic filter via warp-level mma.sync (fp16 HMMA, f32 acc).
//   out[b,y,x,co] = sum_{dy,dx,ci} X[b,y+dy,x+dx,ci] * K[b,dy,dx,ci,co]
//
// R3: tf32 m16n8k8 -> fp16 m16n8k16 (same 11-bit significand => same rel_err,
// 2x tensor rate, 1/2 SMEM traffic). A staged as f16 with permuted k-words so
// fragments load as LDS.64; B pre-packed in fragment order (LDS.128).
// 12 stages of K=32; A double-buffered (regs->STS), B triple-buffered cp.async.
// 96KB SMEM -> 2 CTAs/SM. CTA = (y,b): M=128 px x N=128 Cout; dx taps via
// shifted A-fragment rows.
// ============================================================================

#define THREADS 256

// filter, f16 fragment order: [b][dy][c16(4)][dx(3)][j(2)][pair(8)][lane(32)] x uint4
__device__ uint4 g_Kf4[16 * 3 * 4 * 3 * 2 * 8 * 32];

static __device__ __forceinline__ uint32_t smem_u32(const void* p) {
    uint32_t a;
    asm("{ .reg .u64 t; cvta.to.shared.u64 t, %1; cvt.u32.u64 %0, t; }"
        : "=r"(a) : "l"(p));
    return a;
}

static __device__ __forceinline__ uint32_t pack_h2(float lo, float hi) {
    __half2 h = __floats2half2_rn(lo, hi);
    return *reinterpret_cast<uint32_t*>(&h);
}

static __device__ __forceinline__ void cp16(uint32_t dst, const void* src) {
    asm volatile("cp.async.cg.shared.global [%0], [%1], 16;"
                 :: "r"(dst), "l"(src) : "memory");
}

#define CP_COMMIT() asm volatile("cp.async.commit_group;" ::: "memory")
#define CP_WAIT1()  asm volatile("cp.async.wait_group 1;" ::: "memory")

// D += A * B   (m16n8k16, f16 in, f32 acc)
#define MMA(d, a0, a1, a2, a3, b0, b1)                                        \
    asm volatile(                                                             \
        "mma.sync.aligned.m16n8k16.row.col.f32.f16.f16.f32 "                  \
        "{%0,%1,%2,%3}, {%4,%5,%6,%7}, {%8,%9}, {%0,%1,%2,%3};"               \
        : "+f"((d)[0]), "+f"((d)[1]), "+f"((d)[2]), "+f"((d)[3])              \
        : "r"(a0), "r"(a1), "r"(a2), "r"(a3), "r"(b0), "r"(b1))

// ---------------- pre-pass: filter -> f16 fragment order --------------------
// id -> (b,dy,c16,dx,j,pair,lane). For n-tiles {2p,2p+1} (co = P*16+g, +8):
//   v.x = {K[k0][co0], K[k0+1][co0]}   v.y = {K[k1][co0], K[k1+1][co0]}
//   v.z/.w = same at co0+8;  k0 = c16*32 + j*16 + 2t, k1 = k0 + 8.

__global__ void __launch_bounds__(256) kt_frag(const float* __restrict__ K) {
    int id = blockIdx.x * 256 + threadIdx.x;          // 0 .. 294911
    int lane = id & 31;
    int r = id >> 5;
    int p   = r & 7;  r >>= 3;
    int j   = r & 1;  r >>= 1;
    int dx  = r % 3;  r /= 3;
    int c16 = r & 3;  r >>= 2;
    int dy  = r % 3;
    int b   = r / 3;
    int g = lane >> 2, t = lane & 3;
    int k0  = c16 * 32 + j * 16 + 2 * t;
    int k1  = k0 + 8;
    int co0 = p * 16 + g;
    const float* src = K + ((size_t)(b * 9 + dy * 3 + dx) * 128) * 128;
    uint4 v;
    v.x = pack_h2(src[(size_t)k0 * 128 + co0], src[(size_t)(k0 + 1) * 128 + co0]);
    v.y = pack_h2(src[(size_t)k1 * 128 + co0], src[(size_t)(k1 + 1) * 128 + co0]);
    v.z = pack_h2(src[(size_t)k0 * 128 + co0 + 8], src[(size_t)(k0 + 1) * 128 + co0 + 8]);
    v.w = pack_h2(src[(size_t)k1 * 128 + co0 + 8], src[(size_t)(k1 + 1) * 128 + co0 + 8]);
    g_Kf4[id] = v;
}

// ---------------- main kernel ----------------------------------------------

// A tile: 128 px rows x 32 f16 (=16 words), permuted word order per kstep so
// that (a0,a2)/(a1,a3) fragment pairs are adjacent -> LDS.64.
// Row stride 24 words (96B): g*24 mod 32 ∈ {0,8,16,24} -> conflict-free.
static constexpr int A_STRIDE_W = 24;
static constexpr int A_BYTES    = 128 * A_STRIDE_W * 4;   // 12288
static constexpr int B_BYTES    = 3 * 2 * 8 * 32 * 16;    // 24576
static constexpr int SMEM_B0    = 2 * A_BYTES;            // 24576
static constexpr int SMEM_TOTAL = SMEM_B0 + 3 * B_BYTES;  // 98304

__global__ void __launch_bounds__(THREADS, 2) conv_main(
    const float* __restrict__ X, float* __restrict__ out) {
    extern __shared__ char smem[];
    const uint32_t smem_base = smem_u32(smem);
    const int tid  = threadIdx.x;
    const int lane = tid & 31;
    const int wid  = tid >> 5;
    const int warp_m = wid & 3;           // 4 warps along M (32 rows each)
    const int warp_n = wid >> 2;          // 2 warps along N (64 cols each)
    const int g = lane >> 2, t = lane & 3;
    const int y = blockIdx.x;             // output row 0..125
    const int b = blockIdx.y;             // batch

    const float* Xbase = X + (((size_t)b * 128 + y) * 128) * 128;

    // A staging geometry: 1024 float4 per stage; ch = tid&7 invariant across i.
    const int apx  = tid >> 3;            // base px (+32 per i)
    const int ach  = tid & 7;             // float4 within row (floats 4ch..4ch+3)
    const int aj   = ach >> 2;            // kstep
    const int ac   = ach & 3;
    const int ao0  = ((ac & 1) << 2) + (ac >> 1);          // permuted pos of word 2ac
    const int awrd = apx * A_STRIDE_W + aj * 8 + ao0;      // dest word (+2 for 2nd)

    uint32_t ah[8];  // held A data (pre-converted half2 words)

    auto a_ldg = [&](int s) {
        const int dy = s >> 2, c16 = s & 3;
        const float* Arow = Xbase + (size_t)dy * 16384 + c16 * 32;
#pragma unroll
        for (int i = 0; i < 4; i++) {
            float4 v = *reinterpret_cast<const float4*>(
                Arow + (size_t)(apx + 32 * i) * 128 + ach * 4);
            ah[2 * i]     = pack_h2(v.x, v.y);
            ah[2 * i + 1] = pack_h2(v.z, v.w);
        }
    };
    auto a_sts = [&](int buf) {
        uint32_t* As = reinterpret_cast<uint32_t*>(smem + buf * A_BYTES);
#pragma unroll
        for (int i = 0; i < 4; i++) {
            As[awrd + i * 32 * A_STRIDE_W]     = ah[2 * i];
            As[awrd + i * 32 * A_STRIDE_W + 2] = ah[2 * i + 1];
        }
    };
    auto b_cp = [&](int s) {
        const int dy = s >> 2, c16 = s & 3;
        const uint4* Bsrc = g_Kf4 + ((size_t)((b * 3 + dy) * 4 + c16)) * 1536;
        const uint32_t bb = smem_base + SMEM_B0 + (s % 3) * B_BYTES;
#pragma unroll
        for (int i = 0; i < 6; i++) {
            int idx = tid + i * THREADS;          // 0..1535 uint4s
            cp16(bb + idx * 16, Bsrc + idx);
        }
    };

    float acc[2][8][4];
#pragma unroll
    for (int mt = 0; mt < 2; mt++)
#pragma unroll
        for (int nt = 0; nt < 8; nt++)
#pragma unroll
            for (int e = 0; e < 4; e++) acc[mt][nt][e] = 0.0f;

    // ---- prologue ----
    a_ldg(0); a_sts(0);
    a_ldg(1);                     // stage 1 held in regs
    b_cp(0); CP_COMMIT();
    b_cp(1); CP_COMMIT();

    const int rbase = warp_m * 32 + g;

    for (int s = 0; s < 12; s++) {
        CP_WAIT1();
        __syncthreads();

        if (s < 11) a_sts((s + 1) & 1);
        if (s < 10) { a_ldg(s + 2); b_cp(s + 2); }
        CP_COMMIT();

        const uint32_t* Au = reinterpret_cast<const uint32_t*>(smem + (s & 1) * A_BYTES);
        const uint4*    Bs = reinterpret_cast<const uint4*>(smem + SMEM_B0 + (s % 3) * B_BYTES);

#pragma unroll
        for (int dx = 0; dx < 3; dx++) {
            const int rA = rbase + dx;                 // <= 105
            const int rB = rA + 8;                     // <= 113
            const int rC = rA + 16;                    // <= 121
            const int rD = min(rA + 24, 127);          // clamp (garbage rows)
#pragma unroll
            for (int j = 0; j < 2; j++) {
                const int ko = j * 8 + 2 * t;
                uint2 f0 = *reinterpret_cast<const uint2*>(Au + rA * A_STRIDE_W + ko);
                uint2 f1 = *reinterpret_cast<const uint2*>(Au + rB * A_STRIDE_W + ko);
                uint2 f2 = *reinterpret_cast<const uint2*>(Au + rC * A_STRIDE_W + ko);
                uint2 f3 = *reinterpret_cast<const uint2*>(Au + rD * A_STRIDE_W + ko);
#pragma unroll
                for (int p = 0; p < 4; p++) {
                    uint4 bv = Bs[((dx * 2 + j) * 8 + warp_n * 4 + p) * 32 + lane];
                    MMA(acc[0][2 * p],     f0.x, f1.x, f0.y, f1.y, bv.x, bv.y);
                    MMA(acc[0][2 * p + 1], f0.x, f1.x, f0.y, f1.y, bv.z, bv.w);
                    MMA(acc[1][2 * p],     f2.x, f3.x, f2.y, f3.y, bv.x, bv.y);
                    MMA(acc[1][2 * p + 1], f2.x, f3.x, f2.y, f3.y, bv.z, bv.w);
                }
            }
        }
        __syncthreads();
    }

    // ---- epilogue: direct STG (accumulator rows ARE output x) ----
    float* outp = out + (((size_t)b * 126 + y) * 126) * 128;
#pragma unroll
    for (int mt = 0; mt < 2; mt++) {
        const int x0 = warp_m * 32 + mt * 16 + g;        // always < 126
        const int x1 = x0 + 8;                           // may be 126/127
#pragma unroll
        for (int nt = 0; nt < 8; nt++) {
            const int co = warp_n * 64 + nt * 8 + 2 * t;
            float2 v0 = make_float2(acc[mt][nt][0], acc[mt][nt][1]);
            *reinterpret_cast<float2*>(outp + (size_t)x0 * 128 + co) = v0;
            if (x1 < 126) {
                float2 v1 = make_float2(acc[mt][nt][2], acc[mt][nt][3]);
                *reinterpret_cast<float2*>(outp + (size_t)x1 * 128 + co) = v1;
            }
        }
    }
}

// ---------------- launch ----------------------------------------------------

extern "C" void kernel_launch(void* const* d_in, const int* in_sizes, int n_in,
                              void* d_out, int out_size) {
    const float* X = (const float*)d_in[0];     // [16,128,128,128]
    const float* K = (const float*)d_in[1];     // [16,3,3,128,128]
    float* out = (float*)d_out;                 // [16,126,126,128]
    (void)in_sizes; (void)n_in; (void)out_size;

    cudaFuncSetAttribute(conv_main, cudaFuncAttributeMaxDynamicSharedMemorySize, SMEM_TOTAL);

    kt_frag<<<1152, 256>>>(K);
    conv_main<<<dim3(126, 16), THREADS, SMEM_TOTAL>>>(X, out);
}

// round 5
// speedup vs baseline: 1.7888x; 1.0271x over previous
#include <cuda_runtime.h>
#include <cuda_fp16.h>
#include <cstdint>

// ============================================================================
// Conv2D per-sample dynamic filter via warp-level mma.sync (fp16 HMMA, f32 acc).
//   out[b,y,x,co] = sum_{dy,dx,ci} X[b,y+dy,x+dx,ci] * K[b,dy,dx,ci,co]
//
// R4->R5: one barrier per stage (removed redundant bottom sync); A tile padded
// to 130 rows (kills min() clamp -> all LDS become base+immediate); staging
// burst sandwiched between dx=0 and dx=1 MMA blocks; per-warp base pointers
// precomputed (IMAD address math off the hot path).
// ============================================================================

#define THREADS 256

// filter, f16 fragment order: [b][dy][c16(4)][dx(3)][j(2)][pair(8)][lane(32)] x uint4
__device__ uint4 g_Kf4[16 * 3 * 4 * 3 * 2 * 8 * 32];

static __device__ __forceinline__ uint32_t smem_u32(const void* p) {
    uint32_t a;
    asm("{ .reg .u64 t; cvta.to.shared.u64 t, %1; cvt.u32.u64 %0, t; }"
        : "=r"(a) : "l"(p));
    return a;
}

static __device__ __forceinline__ uint32_t pack_h2(float lo, float hi) {
    __half2 h = __floats2half2_rn(lo, hi);
    return *reinterpret_cast<uint32_t*>(&h);
}

static __device__ __forceinline__ void cp16(uint32_t dst, const void* src) {
    asm volatile("cp.async.cg.shared.global [%0], [%1], 16;"
                 :: "r"(dst), "l"(src) : "memory");
}

#define CP_COMMIT() asm volatile("cp.async.commit_group;" ::: "memory")
#define CP_WAIT1()  asm volatile("cp.async.wait_group 1;" ::: "memory")

// D += A * B   (m16n8k16, f16 in, f32 acc)
#define MMA(d, a0, a1, a2, a3, b0, b1)                                        \
    asm volatile(                                                             \
        "mma.sync.aligned.m16n8k16.row.col.f32.f16.f16.f32 "                  \
        "{%0,%1,%2,%3}, {%4,%5,%6,%7}, {%8,%9}, {%0,%1,%2,%3};"               \
        : "+f"((d)[0]), "+f"((d)[1]), "+f"((d)[2]), "+f"((d)[3])              \
        : "r"(a0), "r"(a1), "r"(a2), "r"(a3), "r"(b0), "r"(b1))

// ---------------- pre-pass: filter -> f16 fragment order --------------------

__global__ void __launch_bounds__(256) kt_frag(const float* __restrict__ K) {
    int id = blockIdx.x * 256 + threadIdx.x;          // 0 .. 294911
    int lane = id & 31;
    int r = id >> 5;
    int p   = r & 7;  r >>= 3;
    int j   = r & 1;  r >>= 1;
    int dx  = r % 3;  r /= 3;
    int c16 = r & 3;  r >>= 2;
    int dy  = r % 3;
    int b   = r / 3;
    int g = lane >> 2, t = lane & 3;
    int k0  = c16 * 32 + j * 16 + 2 * t;
    int k1  = k0 + 8;
    int co0 = p * 16 + g;
    const float* src = K + ((size_t)(b * 9 + dy * 3 + dx) * 128) * 128;
    uint4 v;
    v.x = pack_h2(src[(size_t)k0 * 128 + co0], src[(size_t)(k0 + 1) * 128 + co0]);
    v.y = pack_h2(src[(size_t)k1 * 128 + co0], src[(size_t)(k1 + 1) * 128 + co0]);
    v.z = pack_h2(src[(size_t)k0 * 128 + co0 + 8], src[(size_t)(k0 + 1) * 128 + co0 + 8]);
    v.w = pack_h2(src[(size_t)k1 * 128 + co0 + 8], src[(size_t)(k1 + 1) * 128 + co0 + 8]);
    g_Kf4[id] = v;
}

// ---------------- main kernel ----------------------------------------------

// A tile: 130 px rows (128 real + 2 zero pad) x 32 f16, permuted k-word order.
// Row stride 24 words: g*24 mod 32 in {0,8,16,24} -> conflict-free.
static constexpr int A_STRIDE_W = 24;
static constexpr int A_BYTES    = 12544;                  // 130*96=12480, padded
static constexpr int B_BYTES    = 3 * 2 * 8 * 32 * 16;    // 24576
static constexpr int SMEM_B0    = 2 * A_BYTES;            // 25088
static constexpr int SMEM_TOTAL = SMEM_B0 + 3 * B_BYTES;  // 98816

__global__ void __launch_bounds__(THREADS, 2) conv_main(
    const float* __restrict__ X, float* __restrict__ out) {
    extern __shared__ char smem[];
    const uint32_t smem_base = smem_u32(smem);
    const int tid  = threadIdx.x;
    const int lane = tid & 31;
    const int wid  = tid >> 5;
    const int warp_m = wid & 3;           // 4 warps along M (32 rows each)
    const int warp_n = wid >> 2;          // 2 warps along N (64 cols each)
    const int g = lane >> 2, t = lane & 3;
    const int y = blockIdx.x;             // output row 0..125
    const int b = blockIdx.y;             // batch

    const float* Xbase = X + (((size_t)b * 128 + y) * 128) * 128;

    // zero the 2 pad rows (128,129) of both A buffers (feed only discarded acc)
    if (tid < 96) {
        int buf = tid / 48, w = tid % 48;
        reinterpret_cast<uint32_t*>(smem + buf * A_BYTES)[128 * A_STRIDE_W + w] = 0;
    }

    // A staging geometry: 1024 float4 per stage
    const int apx  = tid >> 3;            // base px (+32 per i)
    const int ach  = tid & 7;
    const int aj   = ach >> 2;
    const int ac   = ach & 3;
    const int ao0  = ((ac & 1) << 2) + (ac >> 1);
    const int awrd = apx * A_STRIDE_W + aj * 8 + ao0;

    uint32_t ah[8];  // held A data (pre-converted half2 words)

    auto a_ldg = [&](int s) {
        const int dy = s >> 2, c16 = s & 3;
        const float* Arow = Xbase + (size_t)dy * 16384 + c16 * 32;
#pragma unroll
        for (int i = 0; i < 4; i++) {
            float4 v = *reinterpret_cast<const float4*>(
                Arow + (size_t)(apx + 32 * i) * 128 + ach * 4);
            ah[2 * i]     = pack_h2(v.x, v.y);
            ah[2 * i + 1] = pack_h2(v.z, v.w);
        }
    };
    auto a_sts = [&](int buf) {
        uint32_t* As = reinterpret_cast<uint32_t*>(smem + buf * A_BYTES);
#pragma unroll
        for (int i = 0; i < 4; i++) {
            As[awrd + i * 32 * A_STRIDE_W]     = ah[2 * i];
            As[awrd + i * 32 * A_STRIDE_W + 2] = ah[2 * i + 1];
        }
    };
    auto b_cp = [&](int s) {
        const int dy = s >> 2, c16 = s & 3;
        const uint4* Bsrc = g_Kf4 + ((size_t)((b * 3 + dy) * 4 + c16)) * 1536;
        const uint32_t bb = smem_base + SMEM_B0 + (s % 3) * B_BYTES;
#pragma unroll
        for (int i = 0; i < 6; i++) {
            int idx = tid + i * THREADS;
            cp16(bb + idx * 16, Bsrc + idx);
        }
    };

    float acc[2][8][4];
#pragma unroll
    for (int mt = 0; mt < 2; mt++)
#pragma unroll
        for (int nt = 0; nt < 8; nt++)
#pragma unroll
            for (int e = 0; e < 4; e++) acc[mt][nt][e] = 0.0f;

    // ---- prologue ----
    a_ldg(0); a_sts(0);
    a_ldg(1);                     // stage 1 held in regs
    b_cp(0); CP_COMMIT();
    b_cp(1); CP_COMMIT();

    // per-warp hot-loop base pointers (all inner LDS become base + immediate)
    const int rbase = warp_m * 32 + g;
    const uint32_t* A0 = reinterpret_cast<const uint32_t*>(smem) + rbase * A_STRIDE_W + 2 * t;
    const uint32_t* A1 = reinterpret_cast<const uint32_t*>(smem + A_BYTES) + rbase * A_STRIDE_W + 2 * t;
    const uint4* Bb0 = reinterpret_cast<const uint4*>(smem + SMEM_B0) + warp_n * 128 + lane;
    const uint4* Bb1 = reinterpret_cast<const uint4*>(smem + SMEM_B0 + B_BYTES) + warp_n * 128 + lane;
    const uint4* Bb2 = reinterpret_cast<const uint4*>(smem + SMEM_B0 + 2 * B_BYTES) + warp_n * 128 + lane;

    for (int s = 0; s < 12; s++) {
        CP_WAIT1();
        __syncthreads();

        const uint32_t* Au = (s & 1) ? A1 : A0;
        const int sm3 = s % 3;
        const uint4* Bs = (sm3 == 0) ? Bb0 : (sm3 == 1) ? Bb1 : Bb2;

        auto do_dx = [&](int dx) {
#pragma unroll
            for (int j = 0; j < 2; j++) {
                const int ro = dx * A_STRIDE_W + j * 8;
                uint2 f0 = *reinterpret_cast<const uint2*>(Au + ro);
                uint2 f1 = *reinterpret_cast<const uint2*>(Au + ro + 8 * A_STRIDE_W);
                uint2 f2 = *reinterpret_cast<const uint2*>(Au + ro + 16 * A_STRIDE_W);
                uint2 f3 = *reinterpret_cast<const uint2*>(Au + ro + 24 * A_STRIDE_W);
#pragma unroll
                for (int p = 0; p < 4; p++) {
                    uint4 bv = Bs[((dx * 2 + j) * 8 + p) * 32];
                    MMA(acc[0][2 * p],     f0.x, f1.x, f0.y, f1.y, bv.x, bv.y);
                    MMA(acc[0][2 * p + 1], f0.x, f1.x, f0.y, f1.y, bv.z, bv.w);
                    MMA(acc[1][2 * p],     f2.x, f3.x, f2.y, f3.y, bv.x, bv.y);
                    MMA(acc[1][2 * p + 1], f2.x, f3.x, f2.y, f3.y, bv.z, bv.w);
                }
            }
        };

        do_dx(0);
        // staging burst hidden under dx=1/2 tensor work
        if (s < 11) a_sts((s + 1) & 1);
        if (s < 10) { a_ldg(s + 2); b_cp(s + 2); }
        CP_COMMIT();
        do_dx(1);
        do_dx(2);
    }

    // ---- epilogue: direct STG (accumulator rows ARE output x) ----
    float* outp = out + (((size_t)b * 126 + y) * 126) * 128;
#pragma unroll
    for (int mt = 0; mt < 2; mt++) {
        const int x0 = warp_m * 32 + mt * 16 + g;        // always < 126
        const int x1 = x0 + 8;                           // may be 126/127
#pragma unroll
        for (int nt = 0; nt < 8; nt++) {
            const int co = warp_n * 64 + nt * 8 + 2 * t;
            float2 v0 = make_float2(acc[mt][nt][0], acc[mt][nt][1]);
            *reinterpret_cast<float2*>(outp + (size_t)x0 * 128 + co) = v0;
            if (x1 < 126) {
                float2 v1 = make_float2(acc[mt][nt][2], acc[mt][nt][3]);
                *reinterpret_cast<float2*>(outp + (size_t)x1 * 128 + co) = v1;
            }
        }
    }
}

// ---------------- launch ----------------------------------------------------

extern "C" void kernel_launch(void* const* d_in, const int* in_sizes, int n_in,
                              void* d_out, int out_size) {
    const float* X = (const float*)d_in[0];     // [16,128,128,128]
    const float* K = (const float*)d_in[1];     // [16,3,3,128,128]
    float* out = (float*)d_out;                 // [16,126,126,128]
    (void)in_sizes; (void)n_in; (void)out_size;

    cudaFuncSetAttribute(conv_main, cudaFuncAttributeMaxDynamicSharedMemorySize, SMEM_TOTAL);

    kt_frag<<<1152, 256>>>(K);
    conv_main<<<dim3(126, 16), THREADS, SMEM_TOTAL>>>(X, out);
}